// round 14
// baseline (speedup 1.0000x reference)
#include <cuda_runtime.h>
#include <cuda_bf16.h>
#include <cstdint>

#define TOKENS 32768
#define DMODEL 4096
#define NEXP   64
#define BM     128
#define BK     32
#define XPITCH 132               // xs row pitch: 16B-aligned rows
#define WPITCH 132               // wd row pitch (128 dup'd floats + pad)
#define NSLAB  (DMODEL / BK)     // 128
#define NBLK_B (TOKENS / 256)    // 128 blocks in the gate kernel
#define MAXR   256               // rescue list capacity
#define EPS_MARGIN 2e-4f         // rescue threshold on noisy top1-top2 margin

// Scratch (no allocations allowed)
__device__ float g_h[TOKENS * NEXP];
__device__ float g_imp[NBLK_B * NEXP];
__device__ int   g_load[NBLK_B * NEXP];
__device__ int   g_rescue_cnt;
__device__ int   g_rescue_list[MAXR];
__device__ int   g_load_delta[NEXP];

// ---- packed f32x2 helpers (FFMA2 — only reachable via PTX fma.rn.f32x2) ----
static __device__ __forceinline__ void unpack2(unsigned long long v, float& lo, float& hi) {
    asm("mov.b64 {%0, %1}, %2;" : "=f"(lo), "=f"(hi) : "l"(v));
}
static __device__ __forceinline__ void ffma2(unsigned long long& d,
                                             unsigned long long a,
                                             unsigned long long b) {
    asm("fma.rn.f32x2 %0, %1, %2, %0;" : "+l"(d) : "l"(a), "l"(b));
}

// ============================================================================
// Kernel A: h = tanh(x @ w1^T)   [32768,4096] x [64,4096]^T -> [32768,64]
//
// R5 skeleton (the measured-best mapping) with two deltas:
//   (1) w staged DUPLICATED in shared (wd[k][2e]=wd[k][2e+1]=w1[e][k]) so the
//       B-operand loads f32x2-ready -> the 8 pack MOVs per k are gone.
//       Inner loop per k: 2 A-LDS.128 (half-warp dedup broadcast) +
//       2 B-LDS.128 (2-addr broadcast) + 16 FFMA2 = 20 issue slots.
//   (2) BK=32 -> half the barriers of R5.
// 256 threads, tile 128 tok x 64 exp, per-thread 8 tok x 4 exp, 2 CTAs/SM.
//   tid&15 -> token group (8 consecutive tokens); (tid>>4)*4 -> expert group.
// ============================================================================
__global__ void __launch_bounds__(256, 2)
gemm1_tanh(const float* __restrict__ x, const float* __restrict__ w1) {
    __shared__ __align__(16) float xs[BK][XPITCH];  // xs[k][token]
    __shared__ __align__(16) float wd[BK][WPITCH];  // wd[k][2e]=wd[k][2e+1]=w1[e][k]

    const int tid = threadIdx.x;
    const int bm  = blockIdx.x * BM;
    const int tg  = tid & 15;              // token group: tokens tg*8 .. tg*8+7
    const int e0  = (tid >> 4) * 4;        // experts e0..e0+3

    // rescue-state reset (gate runs strictly after gemm1 in stream order)
    if (blockIdx.x == 0) {
        if (tid == 0) g_rescue_cnt = 0;
        if (tid < NEXP) g_load_delta[tid] = 0;
    }

    unsigned long long acc[4][4];          // [token-pair][expert]
#pragma unroll
    for (int p = 0; p < 4; p++)
#pragma unroll
        for (int e = 0; e < 4; e++) acc[p][e] = 0ull;

    // loader coords (R5-style coalesced: warp touches 4 contiguous 128B rows)
    // x: 128 rows x 8 float4-chunks -> 4 LDG.128/thread
    // w: 64 rows x 8 float4-chunks -> 2 LDG.128/thread
    // (l = tid + 256*i; row = l>>3; c4 = l&7 covers k = c4*4..c4*4+3)

    // ---- prologue: load slab 0 ----
    float4 xr[4], wr[2];
#pragma unroll
    for (int i = 0; i < 4; i++) {
        const int l = tid + 256 * i;
        xr[i] = *reinterpret_cast<const float4*>(
            &x[(size_t)(bm + (l >> 3)) * DMODEL + (l & 7) * 4]);
    }
#pragma unroll
    for (int i = 0; i < 2; i++) {
        const int l = tid + 256 * i;
        wr[i] = *reinterpret_cast<const float4*>(
            &w1[(size_t)(l >> 3) * DMODEL + (l & 7) * 4]);
    }

#pragma unroll 1
    for (int sl = 0; sl < NSLAB; sl++) {
        if (sl) __syncthreads();           // all warps done reading previous slab

        // transpose-store x slab
#pragma unroll
        for (int i = 0; i < 4; i++) {
            const int l = tid + 256 * i, row = l >> 3, c4 = l & 7;
            xs[c4 * 4 + 0][row] = xr[i].x;
            xs[c4 * 4 + 1][row] = xr[i].y;
            xs[c4 * 4 + 2][row] = xr[i].z;
            xs[c4 * 4 + 3][row] = xr[i].w;
        }
        // duplicated-store w slab (each value twice -> f32x2-ready operands)
#pragma unroll
        for (int i = 0; i < 2; i++) {
            const int l = tid + 256 * i, er = l >> 3, c4 = l & 7;
            *reinterpret_cast<float2*>(&wd[c4 * 4 + 0][2 * er]) = make_float2(wr[i].x, wr[i].x);
            *reinterpret_cast<float2*>(&wd[c4 * 4 + 1][2 * er]) = make_float2(wr[i].y, wr[i].y);
            *reinterpret_cast<float2*>(&wd[c4 * 4 + 2][2 * er]) = make_float2(wr[i].z, wr[i].z);
            *reinterpret_cast<float2*>(&wd[c4 * 4 + 3][2 * er]) = make_float2(wr[i].w, wr[i].w);
        }
        __syncthreads();

        // prefetch next slab (overlaps compute below)
        if (sl + 1 < NSLAB) {
            const int kk = (sl + 1) * BK;
#pragma unroll
            for (int i = 0; i < 4; i++) {
                const int l = tid + 256 * i;
                xr[i] = *reinterpret_cast<const float4*>(
                    &x[(size_t)(bm + (l >> 3)) * DMODEL + kk + (l & 7) * 4]);
            }
#pragma unroll
            for (int i = 0; i < 2; i++) {
                const int l = tid + 256 * i;
                wr[i] = *reinterpret_cast<const float4*>(
                    &w1[(size_t)(l >> 3) * DMODEL + kk + (l & 7) * 4]);
            }
        }

#pragma unroll
        for (int k = 0; k < BK; k++) {
            // A: 8 tokens = 4 ready pairs, two LDS.128 (half-warp dedup)
            const ulonglong2 xa = *reinterpret_cast<const ulonglong2*>(&xs[k][tg * 8]);
            const ulonglong2 xb = *reinterpret_cast<const ulonglong2*>(&xs[k][tg * 8 + 4]);
            // B: 4 experts = 4 ready dup-packs, two broadcast LDS.128
            const ulonglong2 w01 = *reinterpret_cast<const ulonglong2*>(&wd[k][e0 * 2]);
            const ulonglong2 w23 = *reinterpret_cast<const ulonglong2*>(&wd[k][e0 * 2 + 4]);
            ffma2(acc[0][0], xa.x, w01.x); ffma2(acc[0][1], xa.x, w01.y);
            ffma2(acc[0][2], xa.x, w23.x); ffma2(acc[0][3], xa.x, w23.y);
            ffma2(acc[1][0], xa.y, w01.x); ffma2(acc[1][1], xa.y, w01.y);
            ffma2(acc[1][2], xa.y, w23.x); ffma2(acc[1][3], xa.y, w23.y);
            ffma2(acc[2][0], xb.x, w01.x); ffma2(acc[2][1], xb.x, w01.y);
            ffma2(acc[2][2], xb.x, w23.x); ffma2(acc[2][3], xb.x, w23.y);
            ffma2(acc[3][0], xb.y, w01.x); ffma2(acc[3][1], xb.y, w01.y);
            ffma2(acc[3][2], xb.y, w23.x); ffma2(acc[3][3], xb.y, w23.y);
        }
    }

    // ---- epilogue: tanh + store 8 tokens x 4 experts ----
#pragma unroll
    for (int p = 0; p < 4; p++) {
        float lo[4], hi[4];
#pragma unroll
        for (int e = 0; e < 4; e++) unpack2(acc[p][e], lo[e], hi[e]);
        const int t0 = bm + tg * 8 + 2 * p;
        *reinterpret_cast<float4*>(&g_h[(size_t)t0 * NEXP + e0]) =
            make_float4(tanhf(lo[0]), tanhf(lo[1]), tanhf(lo[2]), tanhf(lo[3]));
        *reinterpret_cast<float4*>(&g_h[(size_t)(t0 + 1) * NEXP + e0]) =
            make_float4(tanhf(hi[0]), tanhf(hi[1]), tanhf(hi[2]), tanhf(hi[3]));
    }
}

// ============================================================================
// Kernel B: logits = h @ w2^T; softmax; argmax(logits+noise); near-tie tokens
// flagged for fp64 rescue; deterministic block partials (no float atomics).
// ============================================================================
__global__ void __launch_bounds__(256)
gate_kernel(const float* __restrict__ w2, const float* __restrict__ noise,
            float* __restrict__ out) {
    __shared__ float w2s[NEXP][NEXP];
    __shared__ float s_imp[8][NEXP];
    __shared__ int   s_load[NEXP];

    const int tid  = threadIdx.x;
    const int warp = tid >> 5;

    for (int i = tid; i < NEXP * NEXP; i += 256) w2s[i >> 6][i & 63] = w2[i];
    if (tid < NEXP) s_load[tid] = 0;
    __syncthreads();

    const int t = blockIdx.x * 256 + tid;

    float l[NEXP];
#pragma unroll
    for (int e = 0; e < NEXP; e++) l[e] = 0.f;

    const float4* hrow = reinterpret_cast<const float4*>(&g_h[(size_t)t * NEXP]);
#pragma unroll 2
    for (int j4 = 0; j4 < 16; j4++) {
        float4 hv = hrow[j4];
#pragma unroll
        for (int e = 0; e < NEXP; e++) {
            l[e] += hv.x * w2s[e][4 * j4 + 0] + hv.y * w2s[e][4 * j4 + 1] +
                    hv.z * w2s[e][4 * j4 + 2] + hv.w * w2s[e][4 * j4 + 3];
        }
    }

    float maxl = l[0];
#pragma unroll
    for (int e = 1; e < NEXP; e++) maxl = fmaxf(maxl, l[e]);

    // argmax of logits + gumbel noise, tracking top-2 margin for rescue
    const float4* nrow = reinterpret_cast<const float4*>(&noise[(size_t)t * NEXP]);
    float best = -3.402823466e38f, second = -3.402823466e38f;
    int   bi   = 0;
#pragma unroll
    for (int e4 = 0; e4 < 16; e4++) {
        float4 nv = nrow[e4];
        float v;
#define STEP(COMP, OFF)                                                        \
        v = l[4 * e4 + OFF] + nv.COMP;                                         \
        if (v > best) { second = best; best = v; bi = 4 * e4 + OFF; }          \
        else if (v > second) { second = v; }
        STEP(x, 0) STEP(y, 1) STEP(z, 2) STEP(w, 3)
#undef STEP
    }
    if (best - second < EPS_MARGIN) {
        int idx = atomicAdd(&g_rescue_cnt, 1);
        if (idx < MAXR) g_rescue_list[idx] = t;
    }

    float Z = 0.f;
#pragma unroll
    for (int e = 0; e < NEXP; e++) Z += expf(l[e] - maxl);
    const float inv = 1.0f / Z;

#pragma unroll
    for (int e = 0; e < NEXP; e++) {
        float v = expf(l[e] - maxl) * inv;
        v += __shfl_xor_sync(0xffffffffu, v, 16);
        v += __shfl_xor_sync(0xffffffffu, v, 8);
        v += __shfl_xor_sync(0xffffffffu, v, 4);
        v += __shfl_xor_sync(0xffffffffu, v, 2);
        v += __shfl_xor_sync(0xffffffffu, v, 1);
        if ((tid & 31) == 0) s_imp[warp][e] = v;
    }

    atomicAdd(&s_load[bi], 1);   // integer atomics: deterministic

    out[t]          = (float)bi;
    out[TOKENS + t] = best;

    __syncthreads();
    if (tid < NEXP) {
        float s = 0.f;
#pragma unroll
        for (int w = 0; w < 8; w++) s += s_imp[w][tid];
        g_imp[blockIdx.x * NEXP + tid]  = s;
        g_load[blockIdx.x * NEXP + tid] = s_load[tid];
    }
}

// ============================================================================
// Rescue: recompute flagged tokens' gate in fp64 straight from inputs,
// patch indices/scores, accumulate integer load deltas. Deterministic.
// ============================================================================
__global__ void __launch_bounds__(256)
rescue_kernel(const float* __restrict__ x, const float* __restrict__ w1,
              const float* __restrict__ w2, const float* __restrict__ noise,
              float* __restrict__ out) {
    int cnt = g_rescue_cnt;
    if (cnt > MAXR) cnt = MAXR;
    if ((int)blockIdx.x >= cnt) return;
    const int t   = g_rescue_list[blockIdx.x];
    const int tid = threadIdx.x;
    const int j   = tid >> 2;     // expert for layer-1 row
    const int q   = tid & 3;      // k-quarter

    __shared__ double pz[NEXP][4];
    __shared__ double hs[NEXP];
    __shared__ double lv[NEXP];

    const float* xr = x + (size_t)t * DMODEL;
    const float* wr = w1 + (size_t)j * DMODEL;
    double partial = 0.0;
    const int k0 = q * (DMODEL / 4);
#pragma unroll 4
    for (int k = k0; k < k0 + DMODEL / 4; k++)
        partial += (double)xr[k] * (double)wr[k];
    pz[j][q] = partial;
    __syncthreads();

    if (q == 0) {
        double z = ((pz[j][0] + pz[j][1]) + pz[j][2]) + pz[j][3];
        hs[j] = tanh(z);
    }
    __syncthreads();

    if (tid < NEXP) {
        double s = 0.0;
        for (int jj = 0; jj < NEXP; jj++) s += hs[jj] * (double)w2[tid * NEXP + jj];
        lv[tid] = s + (double)noise[(size_t)t * NEXP + tid];
    }
    __syncthreads();

    if (tid == 0) {
        double bv = lv[0];
        int bi = 0;
        for (int e = 1; e < NEXP; e++)
            if (lv[e] > bv) { bv = lv[e]; bi = e; }
        const int old = (int)out[t];
        if (old != bi) {
            atomicAdd(&g_load_delta[old], -1);
            atomicAdd(&g_load_delta[bi], 1);
            out[t] = (float)bi;
        }
        out[TOKENS + t] = (float)bv;
    }
}

// ============================================================================
// Kernel C: finalize — 256 threads, fixed-order 2-stage reduction
// (4 partials of 32 blocks each, then fixed combine) -> deterministic.
// ============================================================================
__global__ void __launch_bounds__(256)
finalize_kernel(float* __restrict__ out) {
    __shared__ float pimp[4][NEXP];
    __shared__ int   pld[4][NEXP];
    __shared__ float red[NEXP];

    const int tid = threadIdx.x;
    const int e   = tid & 63;
    const int q   = tid >> 6;     // 0..3

    float s  = 0.f;
    int   ld = 0;
    for (int b = q * 32; b < q * 32 + 32; b++) {
        s  += g_imp[b * NEXP + e];
        ld += g_load[b * NEXP + e];
    }
    pimp[q][e] = s;
    pld[q][e]  = ld;
    __syncthreads();

    if (tid < NEXP) {
        const float si = ((pimp[0][tid] + pimp[1][tid]) + pimp[2][tid]) + pimp[3][tid];
        const int   li = pld[0][tid] + pld[1][tid] + pld[2][tid] + pld[3][tid]
                         + g_load_delta[tid];
        const float imp_mean  = si * (1.0f / TOKENS);
        const float load_mean = (float)li * (1.0f / TOKENS);
        out[2 * TOKENS + 1 + tid]        = load_mean;
        out[2 * TOKENS + 1 + NEXP + tid] = imp_mean;
        red[tid] = imp_mean * load_mean;
    }
    __syncthreads();
    if (tid == 0) {
        float a = 0.f;
        for (int i = 0; i < NEXP; i++) a += red[i];
        out[2 * TOKENS] = (float)NEXP * a * 0.1f;
    }
}

extern "C" void kernel_launch(void* const* d_in, const int* in_sizes, int n_in,
                              void* d_out, int out_size) {
    const float* x     = (const float*)d_in[0];
    const float* w1    = (const float*)d_in[1];
    const float* w2    = (const float*)d_in[2];
    const float* noise = (const float*)d_in[3];
    float* out = (float*)d_out;

    gemm1_tanh<<<TOKENS / BM, 256>>>(x, w1);
    gate_kernel<<<NBLK_B, 256>>>(w2, noise, out);
    rescue_kernel<<<MAXR, 256>>>(x, w1, w2, noise, out);
    finalize_kernel<<<1, 256>>>(out);
}

// round 15
// speedup vs baseline: 1.4946x; 1.4946x over previous
#include <cuda_runtime.h>
#include <cuda_bf16.h>
#include <cstdint>

#define TOKENS 32768
#define DMODEL 4096
#define NEXP   64
#define BM     128
#define BK     32
#define PITCH  160               // smem row pitch in floats: =0 mod 32, 16B-aligned
#define NSLAB  (DMODEL / BK)     // 128
#define NBLK_B (TOKENS / 256)    // 128 blocks in the gate kernel
#define MAXR   256               // rescue list capacity
#define EPS_MARGIN 2e-4f         // rescue threshold on noisy top1-top2 margin

// Scratch (no allocations allowed)
__device__ float g_h[TOKENS * NEXP];
__device__ float g_imp[NBLK_B * NEXP];
__device__ int   g_load[NBLK_B * NEXP];
__device__ int   g_rescue_cnt;
__device__ int   g_rescue_list[MAXR];
__device__ int   g_load_delta[NEXP];

// ---- packed f32x2 helpers (FFMA2 — only reachable via PTX fma.rn.f32x2) ----
static __device__ __forceinline__ void unpack2(unsigned long long v, float& lo, float& hi) {
    asm("mov.b64 {%0, %1}, %2;" : "=f"(lo), "=f"(hi) : "l"(v));
}
static __device__ __forceinline__ void ffma2(unsigned long long& d,
                                             unsigned long long a,
                                             unsigned long long b) {
    asm("fma.rn.f32x2 %0, %1, %2, %0;" : "+l"(d) : "l"(a), "l"(b));
}

// per-k-row swizzle: 16B-granular offset, consistent between store and read.
// With PITCH ≡ 0 (mod 32 words), store banks = 4*(m>>2) + row  (all 32 lanes
// distinct -> conflict-free transpose STS); reads stay contiguous + aligned.
#define SWZ(m) ((((m) >> 2) & 7) * 4)

// ============================================================================
// Kernel A: h = tanh(x @ w1^T)   [32768,4096] x [64,4096]^T -> [32768,64]
//
// 256 threads/CTA, tile 128 tok x 64 exp, BK=32, 2 CTAs/SM.
//   lane -> tokens lane*4..lane*4+3 : A = 1 conflict-free LDS.128 (2 ready
//           f32x2 token-pairs)
//   warp -> experts warp*8..+7      : B = 4 warp-uniform (broadcast) LDS.128
//           from wd, where w is staged DUPLICATED ({v,v}) -> f32x2-ready.
// Inner loop per k: 5 LDS.128 + 16 FFMA2, zero packing MOVs, 8 wavefronts.
// All STS staging patterns are bank-conflict-free by construction (see SWZ).
// ============================================================================
__global__ void __launch_bounds__(256, 2)
gemm1_tanh(const float* __restrict__ x, const float* __restrict__ w1) {
    __shared__ __align__(16) float xs[BK * PITCH];  // xs[k][token] (+swz)
    __shared__ __align__(16) float wd[BK * PITCH];  // wd[k][2e]=wd[k][2e+1]=w1[e][k]

    const int tid  = threadIdx.x;
    const int lane = tid & 31;
    const int warp = tid >> 5;
    const int bm   = blockIdx.x * BM;
    const int e0   = warp * 8;             // experts e0..e0+7 (warp-uniform)

    // rescue-state reset (gate runs strictly after gemm1 in stream order)
    if (blockIdx.x == 0) {
        if (tid == 0) g_rescue_cnt = 0;
        if (tid < NEXP) g_load_delta[tid] = 0;
    }

    unsigned long long acc[2][8];          // [token-pair][expert]
#pragma unroll
    for (int p = 0; p < 2; p++)
#pragma unroll
        for (int e = 0; e < 8; e++) acc[p][e] = 0ull;

    // loader coords: slab = BK=32 k's.
    // x: 128 rows x 8 float4-chunks -> 4 LDG.128/thread (coalesced, 4 lines)
    // w: 64 rows x 8 float4-chunks -> 2 LDG.128/thread
    const int lrow = tid >> 3;             // 0..31 (+32*i)
    const int lc4  = tid & 7;              // float4 chunk within slab

    // ---- prologue: load slab 0 ----
    float4 xr[4], wr[2];
#pragma unroll
    for (int i = 0; i < 4; i++)
        xr[i] = *reinterpret_cast<const float4*>(
            &x[(size_t)(bm + lrow + 32 * i) * DMODEL + lc4 * 4]);
#pragma unroll
    for (int i = 0; i < 2; i++)
        wr[i] = *reinterpret_cast<const float4*>(
            &w1[(size_t)(lrow + 32 * i) * DMODEL + lc4 * 4]);

#pragma unroll 1
    for (int sl = 0; sl < NSLAB; sl++) {
        if (sl) __syncthreads();           // all warps done reading previous slab

        // transpose-store x slab: k-row m = lc4*4+j, column = token row.
        // banks = 4*lc4 + row  -> conflict-free STS.32.
#pragma unroll
        for (int i = 0; i < 4; i++) {
            const int row = lrow + 32 * i;
            const float v[4] = { xr[i].x, xr[i].y, xr[i].z, xr[i].w };
#pragma unroll
            for (int j = 0; j < 4; j++) {
                const int m = lc4 * 4 + j;
                xs[m * PITCH + SWZ(m) + row] = v[j];
            }
        }
        // duplicated-store w slab: expert er at columns 2er, 2er+1 ({v,v}).
#pragma unroll
        for (int i = 0; i < 2; i++) {
            const int er = lrow + 32 * i;
            if (er < NEXP) {
                const float v[4] = { wr[i].x, wr[i].y, wr[i].z, wr[i].w };
#pragma unroll
                for (int j = 0; j < 4; j++) {
                    const int m = lc4 * 4 + j;
                    *reinterpret_cast<float2*>(&wd[m * PITCH + SWZ(m) + 2 * er]) =
                        make_float2(v[j], v[j]);
                }
            }
        }
        __syncthreads();

        // prefetch next slab (overlaps compute below)
        if (sl + 1 < NSLAB) {
            const int kk = (sl + 1) * BK;
#pragma unroll
            for (int i = 0; i < 4; i++)
                xr[i] = *reinterpret_cast<const float4*>(
                    &x[(size_t)(bm + lrow + 32 * i) * DMODEL + kk + lc4 * 4]);
#pragma unroll
            for (int i = 0; i < 2; i++)
                wr[i] = *reinterpret_cast<const float4*>(
                    &w1[(size_t)(lrow + 32 * i) * DMODEL + kk + lc4 * 4]);
        }

#pragma unroll
        for (int k = 0; k < BK; k++) {
            const int xb = k * PITCH + SWZ(k);
            // A: 4 tokens = 2 ready pairs, one conflict-free LDS.128
            const ulonglong2 xp = *reinterpret_cast<const ulonglong2*>(&xs[xb + lane * 4]);
            // B: 8 ready dup-packs, four warp-uniform (broadcast) LDS.128
            const float* wb = &wd[xb + e0 * 2];
            const ulonglong2 wA = *reinterpret_cast<const ulonglong2*>(wb);
            const ulonglong2 wB = *reinterpret_cast<const ulonglong2*>(wb + 4);
            const ulonglong2 wC = *reinterpret_cast<const ulonglong2*>(wb + 8);
            const ulonglong2 wD = *reinterpret_cast<const ulonglong2*>(wb + 12);
            ffma2(acc[0][0], xp.x, wA.x); ffma2(acc[0][1], xp.x, wA.y);
            ffma2(acc[0][2], xp.x, wB.x); ffma2(acc[0][3], xp.x, wB.y);
            ffma2(acc[0][4], xp.x, wC.x); ffma2(acc[0][5], xp.x, wC.y);
            ffma2(acc[0][6], xp.x, wD.x); ffma2(acc[0][7], xp.x, wD.y);
            ffma2(acc[1][0], xp.y, wA.x); ffma2(acc[1][1], xp.y, wA.y);
            ffma2(acc[1][2], xp.y, wB.x); ffma2(acc[1][3], xp.y, wB.y);
            ffma2(acc[1][4], xp.y, wC.x); ffma2(acc[1][5], xp.y, wC.y);
            ffma2(acc[1][6], xp.y, wD.x); ffma2(acc[1][7], xp.y, wD.y);
        }
    }

    // ---- epilogue: tanh + store 4 tokens x 8 experts ----
#pragma unroll
    for (int p = 0; p < 2; p++) {
        float lo[8], hi[8];
#pragma unroll
        for (int e = 0; e < 8; e++) unpack2(acc[p][e], lo[e], hi[e]);
        const int t0 = bm + lane * 4 + 2 * p;   // acc.lo = token t0, acc.hi = t0+1
        float* d0 = &g_h[(size_t)t0 * NEXP + e0];
        float* d1 = d0 + NEXP;
        *reinterpret_cast<float4*>(d0) =
            make_float4(tanhf(lo[0]), tanhf(lo[1]), tanhf(lo[2]), tanhf(lo[3]));
        *reinterpret_cast<float4*>(d0 + 4) =
            make_float4(tanhf(lo[4]), tanhf(lo[5]), tanhf(lo[6]), tanhf(lo[7]));
        *reinterpret_cast<float4*>(d1) =
            make_float4(tanhf(hi[0]), tanhf(hi[1]), tanhf(hi[2]), tanhf(hi[3]));
        *reinterpret_cast<float4*>(d1 + 4) =
            make_float4(tanhf(hi[4]), tanhf(hi[5]), tanhf(hi[6]), tanhf(hi[7]));
    }
}

// ============================================================================
// Kernel B: logits = h @ w2^T; softmax; argmax(logits+noise); near-tie tokens
// flagged for fp64 rescue; deterministic block partials (no float atomics).
// ============================================================================
__global__ void __launch_bounds__(256)
gate_kernel(const float* __restrict__ w2, const float* __restrict__ noise,
            float* __restrict__ out) {
    __shared__ float w2s[NEXP][NEXP];
    __shared__ float s_imp[8][NEXP];
    __shared__ int   s_load[NEXP];

    const int tid  = threadIdx.x;
    const int warp = tid >> 5;

    for (int i = tid; i < NEXP * NEXP; i += 256) w2s[i >> 6][i & 63] = w2[i];
    if (tid < NEXP) s_load[tid] = 0;
    __syncthreads();

    const int t = blockIdx.x * 256 + tid;

    float l[NEXP];
#pragma unroll
    for (int e = 0; e < NEXP; e++) l[e] = 0.f;

    const float4* hrow = reinterpret_cast<const float4*>(&g_h[(size_t)t * NEXP]);
#pragma unroll 2
    for (int j4 = 0; j4 < 16; j4++) {
        float4 hv = hrow[j4];
#pragma unroll
        for (int e = 0; e < NEXP; e++) {
            l[e] += hv.x * w2s[e][4 * j4 + 0] + hv.y * w2s[e][4 * j4 + 1] +
                    hv.z * w2s[e][4 * j4 + 2] + hv.w * w2s[e][4 * j4 + 3];
        }
    }

    float maxl = l[0];
#pragma unroll
    for (int e = 1; e < NEXP; e++) maxl = fmaxf(maxl, l[e]);

    // argmax of logits + gumbel noise, tracking top-2 margin for rescue
    const float4* nrow = reinterpret_cast<const float4*>(&noise[(size_t)t * NEXP]);
    float best = -3.402823466e38f, second = -3.402823466e38f;
    int   bi   = 0;
#pragma unroll
    for (int e4 = 0; e4 < 16; e4++) {
        float4 nv = nrow[e4];
        float v;
#define STEP(COMP, OFF)                                                        \
        v = l[4 * e4 + OFF] + nv.COMP;                                         \
        if (v > best) { second = best; best = v; bi = 4 * e4 + OFF; }          \
        else if (v > second) { second = v; }
        STEP(x, 0) STEP(y, 1) STEP(z, 2) STEP(w, 3)
#undef STEP
    }
    if (best - second < EPS_MARGIN) {
        int idx = atomicAdd(&g_rescue_cnt, 1);
        if (idx < MAXR) g_rescue_list[idx] = t;
    }

    float Z = 0.f;
#pragma unroll
    for (int e = 0; e < NEXP; e++) Z += expf(l[e] - maxl);
    const float inv = 1.0f / Z;

#pragma unroll
    for (int e = 0; e < NEXP; e++) {
        float v = expf(l[e] - maxl) * inv;
        v += __shfl_xor_sync(0xffffffffu, v, 16);
        v += __shfl_xor_sync(0xffffffffu, v, 8);
        v += __shfl_xor_sync(0xffffffffu, v, 4);
        v += __shfl_xor_sync(0xffffffffu, v, 2);
        v += __shfl_xor_sync(0xffffffffu, v, 1);
        if ((tid & 31) == 0) s_imp[warp][e] = v;
    }

    atomicAdd(&s_load[bi], 1);   // integer atomics: deterministic

    out[t]          = (float)bi;
    out[TOKENS + t] = best;

    __syncthreads();
    if (tid < NEXP) {
        float s = 0.f;
#pragma unroll
        for (int w = 0; w < 8; w++) s += s_imp[w][tid];
        g_imp[blockIdx.x * NEXP + tid]  = s;
        g_load[blockIdx.x * NEXP + tid] = s_load[tid];
    }
}

// ============================================================================
// Rescue: recompute flagged tokens' gate in fp64 straight from inputs,
// patch indices/scores, accumulate integer load deltas. Deterministic.
// ============================================================================
__global__ void __launch_bounds__(256)
rescue_kernel(const float* __restrict__ x, const float* __restrict__ w1,
              const float* __restrict__ w2, const float* __restrict__ noise,
              float* __restrict__ out) {
    int cnt = g_rescue_cnt;
    if (cnt > MAXR) cnt = MAXR;
    if ((int)blockIdx.x >= cnt) return;
    const int t   = g_rescue_list[blockIdx.x];
    const int tid = threadIdx.x;
    const int j   = tid >> 2;     // expert for layer-1 row
    const int q   = tid & 3;      // k-quarter

    __shared__ double pz[NEXP][4];
    __shared__ double hs[NEXP];
    __shared__ double lv[NEXP];

    const float* xr = x + (size_t)t * DMODEL;
    const float* wr = w1 + (size_t)j * DMODEL;
    double partial = 0.0;
    const int k0 = q * (DMODEL / 4);
#pragma unroll 4
    for (int k = k0; k < k0 + DMODEL / 4; k++)
        partial += (double)xr[k] * (double)wr[k];
    pz[j][q] = partial;
    __syncthreads();

    if (q == 0) {
        double z = ((pz[j][0] + pz[j][1]) + pz[j][2]) + pz[j][3];
        hs[j] = tanh(z);
    }
    __syncthreads();

    if (tid < NEXP) {
        double s = 0.0;
        for (int jj = 0; jj < NEXP; jj++) s += hs[jj] * (double)w2[tid * NEXP + jj];
        lv[tid] = s + (double)noise[(size_t)t * NEXP + tid];
    }
    __syncthreads();

    if (tid == 0) {
        double bv = lv[0];
        int bi = 0;
        for (int e = 1; e < NEXP; e++)
            if (lv[e] > bv) { bv = lv[e]; bi = e; }
        const int old = (int)out[t];
        if (old != bi) {
            atomicAdd(&g_load_delta[old], -1);
            atomicAdd(&g_load_delta[bi], 1);
            out[t] = (float)bi;
        }
        out[TOKENS + t] = (float)bv;
    }
}

// ============================================================================
// Kernel C: finalize — 256 threads, fixed-order 2-stage reduction
// (4 partials of 32 blocks each, then fixed combine) -> deterministic.
// ============================================================================
__global__ void __launch_bounds__(256)
finalize_kernel(float* __restrict__ out) {
    __shared__ float pimp[4][NEXP];
    __shared__ int   pld[4][NEXP];
    __shared__ float red[NEXP];

    const int tid = threadIdx.x;
    const int e   = tid & 63;
    const int q   = tid >> 6;     // 0..3

    float s  = 0.f;
    int   ld = 0;
    for (int b = q * 32; b < q * 32 + 32; b++) {
        s  += g_imp[b * NEXP + e];
        ld += g_load[b * NEXP + e];
    }
    pimp[q][e] = s;
    pld[q][e]  = ld;
    __syncthreads();

    if (tid < NEXP) {
        const float si = ((pimp[0][tid] + pimp[1][tid]) + pimp[2][tid]) + pimp[3][tid];
        const int   li = pld[0][tid] + pld[1][tid] + pld[2][tid] + pld[3][tid]
                         + g_load_delta[tid];
        const float imp_mean  = si * (1.0f / TOKENS);
        const float load_mean = (float)li * (1.0f / TOKENS);
        out[2 * TOKENS + 1 + tid]        = load_mean;
        out[2 * TOKENS + 1 + NEXP + tid] = imp_mean;
        red[tid] = imp_mean * load_mean;
    }
    __syncthreads();
    if (tid == 0) {
        float a = 0.f;
        for (int i = 0; i < NEXP; i++) a += red[i];
        out[2 * TOKENS] = (float)NEXP * a * 0.1f;
    }
}

extern "C" void kernel_launch(void* const* d_in, const int* in_sizes, int n_in,
                              void* d_out, int out_size) {
    const float* x     = (const float*)d_in[0];
    const float* w1    = (const float*)d_in[1];
    const float* w2    = (const float*)d_in[2];
    const float* noise = (const float*)d_in[3];
    float* out = (float*)d_out;

    gemm1_tanh<<<TOKENS / BM, 256>>>(x, w1);
    gate_kernel<<<NBLK_B, 256>>>(w2, noise, out);
    rescue_kernel<<<MAXR, 256>>>(x, w1, w2, noise, out);
    finalize_kernel<<<1, 256>>>(out);
}

// round 17
// speedup vs baseline: 1.6313x; 1.0915x over previous
#include <cuda_runtime.h>
#include <cuda_bf16.h>
#include <cstdint>

#define TOKENS 32768
#define DMODEL 4096
#define NEXP   64
#define BM     128
#define BK     16
#define XPAD   140               // 128 + 12: 16B-aligned rows, low STS conflict
#define NBLK_B (TOKENS / 256)    // 128 blocks in the gate kernel
#define MAXR   256               // rescue list capacity
#define EPS_MARGIN 2e-4f         // rescue threshold on noisy top1-top2 margin

// Scratch (no allocations allowed). Zero-initialized at module load; finalize
// resets rescue state at its tail so every graph replay starts clean.
__device__ float g_h[TOKENS * NEXP];
__device__ float g_imp[NBLK_B * NEXP];
__device__ int   g_load[NBLK_B * NEXP];
__device__ int   g_rescue_cnt;
__device__ int   g_rescue_list[MAXR];
__device__ int   g_load_delta[NEXP];

// ---- packed f32x2 helpers (FFMA2 — only reachable via PTX fma.rn.f32x2) ----
static __device__ __forceinline__ unsigned long long pack2(float lo, float hi) {
    unsigned long long r;
    asm("mov.b64 %0, {%1, %2};" : "=l"(r) : "f"(lo), "f"(hi));
    return r;
}
static __device__ __forceinline__ void unpack2(unsigned long long v, float& lo, float& hi) {
    asm("mov.b64 {%0, %1}, %2;" : "=f"(lo), "=f"(hi) : "l"(v));
}
static __device__ __forceinline__ void ffma2(unsigned long long& d,
                                             unsigned long long a,
                                             unsigned long long b) {
    asm("fma.rn.f32x2 %0, %1, %2, %0;" : "+l"(d) : "l"(a), "l"(b));
}

// ============================================================================
// Kernel A: h = tanh(x @ w1^T)  — VERBATIM the round-4 kernel that measured
// 429us / fma 50.4% / regs 114 (no spills). Do not touch without first
// verifying register count stays <= ~110.
// ============================================================================
__global__ void __launch_bounds__(256, 2)
gemm1_tanh(const float* __restrict__ x, const float* __restrict__ w1) {
    __shared__ __align__(16) float xs[BK][XPAD];   // xs[k][token]
    __shared__ __align__(16) float ws[BK][NEXP];   // ws[k][expert]

    const int tid  = threadIdx.x;
    const int lane = tid & 31;
    const int warp = tid >> 5;
    const int bm   = blockIdx.x * BM;
    const int e0   = warp * 8;

    // loader mapping: each thread moves 2 float4 of x and 1 float4 of w per tile
    const int row0 = tid >> 2;        // 0..63
    const int row1 = row0 + 64;       // 64..127
    const int c4   = tid & 3;         // k-chunk within BK (4 floats)

    unsigned long long acc[2][8];     // [token-pair][expert]
#pragma unroll
    for (int p = 0; p < 2; p++)
#pragma unroll
        for (int e = 0; e < 8; e++) acc[p][e] = 0ull;

    // ---- prologue: load tile 0 ----
    float4 xr0 = *reinterpret_cast<const float4*>(&x[(size_t)(bm + row0) * DMODEL + c4 * 4]);
    float4 xr1 = *reinterpret_cast<const float4*>(&x[(size_t)(bm + row1) * DMODEL + c4 * 4]);
    float4 wr  = *reinterpret_cast<const float4*>(&w1[(size_t)row0 * DMODEL + c4 * 4]);

    xs[c4 * 4 + 0][row0] = xr0.x;  xs[c4 * 4 + 1][row0] = xr0.y;
    xs[c4 * 4 + 2][row0] = xr0.z;  xs[c4 * 4 + 3][row0] = xr0.w;
    xs[c4 * 4 + 0][row1] = xr1.x;  xs[c4 * 4 + 1][row1] = xr1.y;
    xs[c4 * 4 + 2][row1] = xr1.z;  xs[c4 * 4 + 3][row1] = xr1.w;
    ws[c4 * 4 + 0][row0] = wr.x;   ws[c4 * 4 + 1][row0] = wr.y;
    ws[c4 * 4 + 2][row0] = wr.z;   ws[c4 * 4 + 3][row0] = wr.w;
    __syncthreads();

    const int NT = DMODEL / BK;   // 256 k-slabs
    for (int kt = 0; kt < NT; kt++) {
        // prefetch next slab into registers (overlaps with compute below)
        if (kt + 1 < NT) {
            const int kk = (kt + 1) * BK;
            xr0 = *reinterpret_cast<const float4*>(&x[(size_t)(bm + row0) * DMODEL + kk + c4 * 4]);
            xr1 = *reinterpret_cast<const float4*>(&x[(size_t)(bm + row1) * DMODEL + kk + c4 * 4]);
            wr  = *reinterpret_cast<const float4*>(&w1[(size_t)row0 * DMODEL + kk + c4 * 4]);
        }

#pragma unroll
        for (int k = 0; k < BK; k++) {
            // 4 tokens = 2 f32x2 pairs, one conflict-free LDS.128
            const ulonglong2 xa = *reinterpret_cast<const ulonglong2*>(&xs[k][lane * 4]);
            // 8 warp-uniform w values (broadcast LDS), duplicated in regs
            const float4 wa = *reinterpret_cast<const float4*>(&ws[k][e0]);
            const float4 wb = *reinterpret_cast<const float4*>(&ws[k][e0 + 4]);
            unsigned long long wd[8];
            wd[0] = pack2(wa.x, wa.x); wd[1] = pack2(wa.y, wa.y);
            wd[2] = pack2(wa.z, wa.z); wd[3] = pack2(wa.w, wa.w);
            wd[4] = pack2(wb.x, wb.x); wd[5] = pack2(wb.y, wb.y);
            wd[6] = pack2(wb.z, wb.z); wd[7] = pack2(wb.w, wb.w);
#pragma unroll
            for (int e = 0; e < 8; e++) {
                ffma2(acc[0][e], xa.x, wd[e]);
                ffma2(acc[1][e], xa.y, wd[e]);
            }
        }

        if (kt + 1 < NT) {
            __syncthreads();   // everyone done reading this slab
            xs[c4 * 4 + 0][row0] = xr0.x;  xs[c4 * 4 + 1][row0] = xr0.y;
            xs[c4 * 4 + 2][row0] = xr0.z;  xs[c4 * 4 + 3][row0] = xr0.w;
            xs[c4 * 4 + 0][row1] = xr1.x;  xs[c4 * 4 + 1][row1] = xr1.y;
            xs[c4 * 4 + 2][row1] = xr1.z;  xs[c4 * 4 + 3][row1] = xr1.w;
            ws[c4 * 4 + 0][row0] = wr.x;   ws[c4 * 4 + 1][row0] = wr.y;
            ws[c4 * 4 + 2][row0] = wr.z;   ws[c4 * 4 + 3][row0] = wr.w;
            __syncthreads();   // slab visible
        }
    }

    // ---- epilogue: tanh + store 4 tokens x 8 experts ----
#pragma unroll
    for (int p = 0; p < 2; p++) {
        float lo[8], hi[8];
#pragma unroll
        for (int e = 0; e < 8; e++) unpack2(acc[p][e], lo[e], hi[e]);
        const int t0 = bm + lane * 4 + 2 * p;
        float* d0 = &g_h[(size_t)t0 * NEXP + e0];
        float* d1 = d0 + NEXP;
        *reinterpret_cast<float4*>(d0) =
            make_float4(tanhf(lo[0]), tanhf(lo[1]), tanhf(lo[2]), tanhf(lo[3]));
        *reinterpret_cast<float4*>(d0 + 4) =
            make_float4(tanhf(lo[4]), tanhf(lo[5]), tanhf(lo[6]), tanhf(lo[7]));
        *reinterpret_cast<float4*>(d1) =
            make_float4(tanhf(hi[0]), tanhf(hi[1]), tanhf(hi[2]), tanhf(hi[3]));
        *reinterpret_cast<float4*>(d1 + 4) =
            make_float4(tanhf(hi[4]), tanhf(hi[5]), tanhf(hi[6]), tanhf(hi[7]));
    }
}

// ============================================================================
// Kernel B: logits = h @ w2^T; softmax; argmax(logits+noise); near-tie tokens
// flagged for fp64 rescue; deterministic block partials (no float atomics).
// ============================================================================
__global__ void __launch_bounds__(256)
gate_kernel(const float* __restrict__ w2, const float* __restrict__ noise,
            float* __restrict__ out) {
    __shared__ float w2s[NEXP][NEXP];
    __shared__ float s_imp[8][NEXP];
    __shared__ int   s_load[NEXP];

    const int tid  = threadIdx.x;
    const int warp = tid >> 5;

    for (int i = tid; i < NEXP * NEXP; i += 256) w2s[i >> 6][i & 63] = w2[i];
    if (tid < NEXP) s_load[tid] = 0;
    __syncthreads();

    const int t = blockIdx.x * 256 + tid;

    float l[NEXP];
#pragma unroll
    for (int e = 0; e < NEXP; e++) l[e] = 0.f;

    const float4* hrow = reinterpret_cast<const float4*>(&g_h[(size_t)t * NEXP]);
#pragma unroll 2
    for (int j4 = 0; j4 < 16; j4++) {
        float4 hv = hrow[j4];
#pragma unroll
        for (int e = 0; e < NEXP; e++) {
            l[e] += hv.x * w2s[e][4 * j4 + 0] + hv.y * w2s[e][4 * j4 + 1] +
                    hv.z * w2s[e][4 * j4 + 2] + hv.w * w2s[e][4 * j4 + 3];
        }
    }

    float maxl = l[0];
#pragma unroll
    for (int e = 1; e < NEXP; e++) maxl = fmaxf(maxl, l[e]);

    // argmax of logits + gumbel noise, tracking top-2 margin for rescue
    const float4* nrow = reinterpret_cast<const float4*>(&noise[(size_t)t * NEXP]);
    float best = -3.402823466e38f, second = -3.402823466e38f;
    int   bi   = 0;
#pragma unroll
    for (int e4 = 0; e4 < 16; e4++) {
        float4 nv = nrow[e4];
        float v;
#define STEP(COMP, OFF)                                                        \
        v = l[4 * e4 + OFF] + nv.COMP;                                         \
        if (v > best) { second = best; best = v; bi = 4 * e4 + OFF; }          \
        else if (v > second) { second = v; }
        STEP(x, 0) STEP(y, 1) STEP(z, 2) STEP(w, 3)
#undef STEP
    }
    if (best - second < EPS_MARGIN) {
        int idx = atomicAdd(&g_rescue_cnt, 1);
        if (idx < MAXR) g_rescue_list[idx] = t;
    }

    float Z = 0.f;
#pragma unroll
    for (int e = 0; e < NEXP; e++) Z += expf(l[e] - maxl);
    const float inv = 1.0f / Z;

#pragma unroll
    for (int e = 0; e < NEXP; e++) {
        float v = expf(l[e] - maxl) * inv;
        v += __shfl_xor_sync(0xffffffffu, v, 16);
        v += __shfl_xor_sync(0xffffffffu, v, 8);
        v += __shfl_xor_sync(0xffffffffu, v, 4);
        v += __shfl_xor_sync(0xffffffffu, v, 2);
        v += __shfl_xor_sync(0xffffffffu, v, 1);
        if ((tid & 31) == 0) s_imp[warp][e] = v;
    }

    atomicAdd(&s_load[bi], 1);   // integer atomics: deterministic

    out[t]          = (float)bi;
    out[TOKENS + t] = best;

    __syncthreads();
    if (tid < NEXP) {
        float s = 0.f;
#pragma unroll
        for (int w = 0; w < 8; w++) s += s_imp[w][tid];
        g_imp[blockIdx.x * NEXP + tid]  = s;
        g_load[blockIdx.x * NEXP + tid] = s_load[tid];
    }
}

// ============================================================================
// Rescue: recompute flagged tokens' gate in fp64 straight from inputs,
// patch indices/scores, accumulate integer load deltas. Deterministic.
// ============================================================================
__global__ void __launch_bounds__(256)
rescue_kernel(const float* __restrict__ x, const float* __restrict__ w1,
              const float* __restrict__ w2, const float* __restrict__ noise,
              float* __restrict__ out) {
    int cnt = g_rescue_cnt;
    if (cnt > MAXR) cnt = MAXR;
    if ((int)blockIdx.x >= cnt) return;
    const int t   = g_rescue_list[blockIdx.x];
    const int tid = threadIdx.x;
    const int j   = tid >> 2;     // expert for layer-1 row
    const int q   = tid & 3;      // k-quarter

    __shared__ double pz[NEXP][4];
    __shared__ double hs[NEXP];
    __shared__ double lv[NEXP];

    const float* xr = x + (size_t)t * DMODEL;
    const float* wr = w1 + (size_t)j * DMODEL;
    double partial = 0.0;
    const int k0 = q * (DMODEL / 4);
#pragma unroll 4
    for (int k = k0; k < k0 + DMODEL / 4; k++)
        partial += (double)xr[k] * (double)wr[k];
    pz[j][q] = partial;
    __syncthreads();

    if (q == 0) {
        double z = ((pz[j][0] + pz[j][1]) + pz[j][2]) + pz[j][3];
        hs[j] = tanh(z);
    }
    __syncthreads();

    if (tid < NEXP) {
        double s = 0.0;
        for (int jj = 0; jj < NEXP; jj++) s += hs[jj] * (double)w2[tid * NEXP + jj];
        lv[tid] = s + (double)noise[(size_t)t * NEXP + tid];
    }
    __syncthreads();

    if (tid == 0) {
        double bv = lv[0];
        int bi = 0;
        for (int e = 1; e < NEXP; e++)
            if (lv[e] > bv) { bv = lv[e]; bi = e; }
        const int old = (int)out[t];
        if (old != bi) {
            atomicAdd(&g_load_delta[old], -1);
            atomicAdd(&g_load_delta[bi], 1);
            out[t] = (float)bi;
        }
        out[TOKENS + t] = (float)bv;
    }
}

// ============================================================================
// Kernel C: finalize — 256 threads, fixed-order 2-stage reduction, then
// resets rescue state for the next graph replay (runs after rescue consumed
// it; module zero-init covers the very first call).
// ============================================================================
__global__ void __launch_bounds__(256)
finalize_kernel(float* __restrict__ out) {
    __shared__ float pimp[4][NEXP];
    __shared__ int   pld[4][NEXP];
    __shared__ float red[NEXP];

    const int tid = threadIdx.x;
    const int e   = tid & 63;
    const int q   = tid >> 6;     // 0..3

    float s  = 0.f;
    int   ld = 0;
    for (int b = q * 32; b < q * 32 + 32; b++) {
        s  += g_imp[b * NEXP + e];
        ld += g_load[b * NEXP + e];
    }
    pimp[q][e] = s;
    pld[q][e]  = ld;
    __syncthreads();

    if (tid < NEXP) {
        const float si = ((pimp[0][tid] + pimp[1][tid]) + pimp[2][tid]) + pimp[3][tid];
        const int   li = pld[0][tid] + pld[1][tid] + pld[2][tid] + pld[3][tid]
                         + g_load_delta[tid];
        const float imp_mean  = si * (1.0f / TOKENS);
        const float load_mean = (float)li * (1.0f / TOKENS);
        out[2 * TOKENS + 1 + tid]        = load_mean;
        out[2 * TOKENS + 1 + NEXP + tid] = imp_mean;
        red[tid] = imp_mean * load_mean;
        g_load_delta[tid] = 0;            // reset for next replay
    }
    __syncthreads();
    if (tid == 0) {
        float a = 0.f;
        for (int i = 0; i < NEXP; i++) a += red[i];
        out[2 * TOKENS] = (float)NEXP * a * 0.1f;
        g_rescue_cnt = 0;                 // reset for next replay
    }
}

extern "C" void kernel_launch(void* const* d_in, const int* in_sizes, int n_in,
                              void* d_out, int out_size) {
    const float* x     = (const float*)d_in[0];
    const float* w1    = (const float*)d_in[1];
    const float* w2    = (const float*)d_in[2];
    const float* noise = (const float*)d_in[3];
    float* out = (float*)d_out;

    gemm1_tanh<<<TOKENS / BM, 256>>>(x, w1);
    gate_kernel<<<NBLK_B, 256>>>(w2, noise, out);
    rescue_kernel<<<MAXR, 256>>>(x, w1, w2, noise, out);
    finalize_kernel<<<1, 256>>>(out);
}